// round 1
// baseline (speedup 1.0000x reference)
#include <cuda_runtime.h>
#include <cstdint>

// Problem constants
#define P    1024
#define RDIM 128
#define MDIM 128
#define RPB  8          // rows of output per block
#define NTHREADS 512
#define NWARPS (NTHREADS/32)

// Dynamic smem layout (floats):
//   s_w    [128]                     : att_w
//   s_sc   [RPB*1024]                : scores -> exp -> weights
//   s_red  [64]                      : cross-warp max/sum scratch
//   s_part [4*RPB*128]               : phase-3 slice partials (16 KB)
#define SMEM_FLOATS (128 + RPB*1024 + 64 + 4*RPB*128)
#define SMEM_BYTES  (SMEM_FLOATS * 4)

__global__ __launch_bounds__(NTHREADS, 1)
void si_fused_kernel(const float* __restrict__ hidden,
                     const float* __restrict__ rela,
                     const int*   __restrict__ nei,
                     const float* __restrict__ att_w,
                     const float* __restrict__ att_b,
                     float*       __restrict__ out)
{
    extern __shared__ float smem[];
    float* s_w   = smem;                       // 128
    float* s_sc  = smem + 128;                 // RPB * 1024
    float* s_red = s_sc + RPB * 1024;          // 64
    float* s_part= s_red + 64;                 // 4 * RPB * 128

    const int tid  = threadIdx.x;
    const int lane = tid & 31;
    const int warp = tid >> 5;
    const int i0   = blockIdx.x * RPB;

    // ---- load att_w into smem, then each lane keeps its float4 chunk ----
    if (tid < 128) s_w[tid] = att_w[tid];
    __syncthreads();
    const float4 w4 = reinterpret_cast<const float4*>(s_w)[lane];
    const float  b  = att_b[0];

    // =====================================================================
    // Phase 1: scores[r][j] = rela[i0+r, j, :] . att_w + b
    // 8192 dot products, one warp per dot, lanes do float4, shfl-reduce.
    // idx = warp + 16*k keeps adjacent warps on adjacent 512B chunks.
    // =====================================================================
    {
        const float* base = rela + (size_t)i0 * P * RDIM;
        #pragma unroll 1
        for (int k = 0; k < (RPB * P) / NWARPS; k += 2) {
            const int idx0 = warp + (k    ) * NWARPS;
            const int idx1 = warp + (k + 1) * NWARPS;
            const float4 a0 = reinterpret_cast<const float4*>(base + (size_t)idx0 * RDIM)[lane];
            const float4 a1 = reinterpret_cast<const float4*>(base + (size_t)idx1 * RDIM)[lane];
            float d0 = a0.x * w4.x + a0.y * w4.y + a0.z * w4.z + a0.w * w4.w;
            float d1 = a1.x * w4.x + a1.y * w4.y + a1.z * w4.z + a1.w * w4.w;
            #pragma unroll
            for (int s = 16; s; s >>= 1) {
                d0 += __shfl_xor_sync(0xFFFFFFFFu, d0, s);
                d1 += __shfl_xor_sync(0xFFFFFFFFu, d1, s);
            }
            if (lane == 0) {
                s_sc[idx0] = d0 + b;
                s_sc[idx1] = d1 + b;
            }
        }
    }
    __syncthreads();

    // =====================================================================
    // Phase 2: per-row masked softmax. 64 threads (2 warps) per row.
    //   pos = mask ? score : -1e-6 ; softmax over all 1024 j ;
    //   weight = mask ? pos : 0
    // =====================================================================
    {
        const int row  = tid >> 6;        // 0..7
        const int t64  = tid & 63;
        const int wsub = (tid >> 5) & 1;  // which of the 2 warps in this row
        const int* nrow = nei + (size_t)(i0 + row) * P;
        float* sc = s_sc + row * P;

        float vals[16];
        unsigned mbits = 0;
        float vmax = -1e30f;
        #pragma unroll
        for (int k = 0; k < 16; k++) {
            const int j = t64 + k * 64;
            const bool m = (nrow[j] > 0);
            if (m) mbits |= (1u << k);
            const float v = m ? sc[j] : -1e-6f;
            vals[k] = v;
            vmax = fmaxf(vmax, v);
        }
        #pragma unroll
        for (int s = 16; s; s >>= 1)
            vmax = fmaxf(vmax, __shfl_xor_sync(0xFFFFFFFFu, vmax, s));
        if (lane == 0) s_red[row * 2 + wsub] = vmax;
        __syncthreads();
        vmax = fmaxf(s_red[row * 2], s_red[row * 2 + 1]);

        float vsum = 0.0f;
        #pragma unroll
        for (int k = 0; k < 16; k++) {
            const float e = __expf(vals[k] - vmax);
            vals[k] = e;
            vsum += e;
        }
        #pragma unroll
        for (int s = 16; s; s >>= 1)
            vsum += __shfl_xor_sync(0xFFFFFFFFu, vsum, s);
        if (lane == 0) s_red[16 + row * 2 + wsub] = vsum;
        __syncthreads();
        vsum = s_red[16 + row * 2] + s_red[16 + row * 2 + 1];
        const float inv = 1.0f / vsum;

        #pragma unroll
        for (int k = 0; k < 16; k++) {
            const int j = t64 + k * 64;
            sc[j] = ((mbits >> k) & 1u) ? vals[k] * inv : 0.0f;
        }
    }
    __syncthreads();

    // =====================================================================
    // Phase 3: out[i0+r, m] = sum_j W[r][j] * hidden[j][m]
    // 4 slice-groups of 128 threads; each group covers 256 j's for all
    // 8 rows and all 128 m. Weights via LDS.128 broadcast, hidden via LDG.
    // =====================================================================
    {
        const int m     = tid & 127;
        const int slice = tid >> 7;   // 0..3
        const int j0    = slice * 256;

        float acc[RPB];
        #pragma unroll
        for (int r = 0; r < RPB; r++) acc[r] = 0.0f;

        #pragma unroll 1
        for (int j = j0; j < j0 + 256; j += 4) {
            const float h0 = hidden[(size_t)(j + 0) * MDIM + m];
            const float h1 = hidden[(size_t)(j + 1) * MDIM + m];
            const float h2 = hidden[(size_t)(j + 2) * MDIM + m];
            const float h3 = hidden[(size_t)(j + 3) * MDIM + m];
            #pragma unroll
            for (int r = 0; r < RPB; r++) {
                const float4 wv = *reinterpret_cast<const float4*>(&s_sc[r * P + j]);
                acc[r] = fmaf(wv.x, h0, acc[r]);
                acc[r] = fmaf(wv.y, h1, acc[r]);
                acc[r] = fmaf(wv.z, h2, acc[r]);
                acc[r] = fmaf(wv.w, h3, acc[r]);
            }
        }

        #pragma unroll
        for (int r = 0; r < RPB; r++)
            s_part[(slice * RPB + r) * 128 + m] = acc[r];
    }
    __syncthreads();

    // Reduce the 4 slice partials and store.
    for (int o = tid; o < RPB * 128; o += NTHREADS) {
        const int r  = o >> 7;
        const int mm = o & 127;
        const float v = s_part[(0 * RPB + r) * 128 + mm]
                      + s_part[(1 * RPB + r) * 128 + mm]
                      + s_part[(2 * RPB + r) * 128 + mm]
                      + s_part[(3 * RPB + r) * 128 + mm];
        out[(size_t)(i0 + r) * MDIM + mm] = v;
    }
}

extern "C" void kernel_launch(void* const* d_in, const int* in_sizes, int n_in,
                              void* d_out, int out_size)
{
    (void)in_sizes; (void)n_in; (void)out_size;
    const float* hidden = (const float*)d_in[0];   // [1024,128]
    const float* rela   = (const float*)d_in[1];   // [1024,1024,128]
    // d_in[2] = corr_index : unused by reference
    const int*   nei    = (const int*)  d_in[3];   // [1024,1024]
    const float* att_w  = (const float*)d_in[4];   // [128]
    const float* att_b  = (const float*)d_in[5];   // [1]
    float* out = (float*)d_out;                    // [1024,128] f32

    cudaFuncSetAttribute(si_fused_kernel,
                         cudaFuncAttributeMaxDynamicSharedMemorySize,
                         SMEM_BYTES);

    si_fused_kernel<<<P / RPB, NTHREADS, SMEM_BYTES>>>(
        hidden, rela, nei, att_w, att_b, out);
}

// round 2
// speedup vs baseline: 1.4982x; 1.4982x over previous
#include <cuda_runtime.h>
#include <cstdint>

#define P    1024
#define RDIM 128
#define MDIM 128

// 4 MB scratch for scores (device global — allocation-free).
__device__ float g_scores[P * P];

// =====================================================================
// Kernel A: scores[n] = rela_flat[n, :] . att_w + b   for n in [0, P*P)
// Grid 1024 x 256 threads. Each warp owns 128 contiguous rows, processes
// 8 rows per iteration with 8 independent LDG.128 in flight, then a
// batched 8-value butterfly reduce (40 shfls, interleaved by scheduler).
// =====================================================================
__global__ __launch_bounds__(256)
void si_scores_kernel(const float* __restrict__ rela,
                      const float* __restrict__ att_w,
                      const float* __restrict__ att_b)
{
    const int lane = threadIdx.x & 31;
    const int warp = threadIdx.x >> 5;
    const int gw   = blockIdx.x * 8 + warp;       // global warp id (0..8191)
    const size_t base = (size_t)gw * 128;         // first dot-row of this warp

    const float4 w4 = reinterpret_cast<const float4*>(att_w)[lane];
    const float  b  = att_b[0];

    #pragma unroll 1
    for (int it = 0; it < 16; it++) {
        const size_t r0 = base + (size_t)it * 8;

        // 8 independent 512B row loads (32 x 128B lines in flight / warp)
        float4 a[8];
        #pragma unroll
        for (int k = 0; k < 8; k++)
            a[k] = reinterpret_cast<const float4*>(rela + (r0 + k) * RDIM)[lane];

        float d[8];
        #pragma unroll
        for (int k = 0; k < 8; k++)
            d[k] = fmaf(a[k].x, w4.x,
                   fmaf(a[k].y, w4.y,
                   fmaf(a[k].z, w4.z, a[k].w * w4.w)));

        // batched butterfly reduce: 5 stages x 8 values
        #pragma unroll
        for (int s = 16; s; s >>= 1) {
            #pragma unroll
            for (int k = 0; k < 8; k++)
                d[k] += __shfl_xor_sync(0xFFFFFFFFu, d[k], s);
        }

        // lane k (k<8) stores row r0+k : coalesced 32B store
        float res = d[0];
        #pragma unroll
        for (int k = 1; k < 8; k++)
            if ((lane & 7) == k) res = d[k];
        if (lane < 8)
            g_scores[r0 + lane] = res + b;
    }
}

// =====================================================================
// Kernel B: per-row masked softmax + weights @ hidden.
// Grid 128 x 512 threads, 8 output rows per block.
// =====================================================================
#define RPB  8
#define NTHREADS 512

// smem floats: s_sc[RPB*1024] + s_red[64] + s_part[4*RPB*128]
#define SMEM_FLOATS (RPB*1024 + 64 + 4*RPB*128)
#define SMEM_BYTES  (SMEM_FLOATS * 4)

__global__ __launch_bounds__(NTHREADS, 1)
void si_softmax_gemm_kernel(const float* __restrict__ hidden,
                            const int*   __restrict__ nei,
                            float*       __restrict__ out)
{
    extern __shared__ float smem[];
    float* s_sc  = smem;                  // RPB * 1024 (weights)
    float* s_red = s_sc + RPB * 1024;     // 64
    float* s_part= s_red + 64;            // 4 * RPB * 128

    const int tid  = threadIdx.x;
    const int lane = tid & 31;
    const int i0   = blockIdx.x * RPB;

    // ---- Phase 2: masked softmax, 64 threads (2 warps) per row ----
    {
        const int row  = tid >> 6;        // 0..7
        const int t64  = tid & 63;
        const int wsub = (tid >> 5) & 1;
        const int*   nrow = nei      + (size_t)(i0 + row) * P;
        const float* srow = g_scores + (size_t)(i0 + row) * P;
        float* sc = s_sc + row * P;

        float vals[16];
        unsigned mbits = 0;
        float vmax = -1e30f;
        #pragma unroll
        for (int k = 0; k < 16; k++) {
            const int j = t64 + k * 64;
            const bool m = (nrow[j] > 0);
            if (m) mbits |= (1u << k);
            const float v = m ? srow[j] : -1e-6f;
            vals[k] = v;
            vmax = fmaxf(vmax, v);
        }
        #pragma unroll
        for (int s = 16; s; s >>= 1)
            vmax = fmaxf(vmax, __shfl_xor_sync(0xFFFFFFFFu, vmax, s));
        if (lane == 0) s_red[row * 2 + wsub] = vmax;
        __syncthreads();
        vmax = fmaxf(s_red[row * 2], s_red[row * 2 + 1]);

        float vsum = 0.0f;
        #pragma unroll
        for (int k = 0; k < 16; k++) {
            const float e = __expf(vals[k] - vmax);
            vals[k] = e;
            vsum += e;
        }
        #pragma unroll
        for (int s = 16; s; s >>= 1)
            vsum += __shfl_xor_sync(0xFFFFFFFFu, vsum, s);
        if (lane == 0) s_red[16 + row * 2 + wsub] = vsum;
        __syncthreads();
        vsum = s_red[16 + row * 2] + s_red[16 + row * 2 + 1];
        const float inv = 1.0f / vsum;

        #pragma unroll
        for (int k = 0; k < 16; k++) {
            const int j = t64 + k * 64;
            sc[j] = ((mbits >> k) & 1u) ? vals[k] * inv : 0.0f;
        }
    }
    __syncthreads();

    // ---- Phase 3: out[i0+r, m] = sum_j W[r][j] * hidden[j][m] ----
    {
        const int m     = tid & 127;
        const int slice = tid >> 7;   // 0..3
        const int j0    = slice * 256;

        float acc[RPB];
        #pragma unroll
        for (int r = 0; r < RPB; r++) acc[r] = 0.0f;

        #pragma unroll 1
        for (int j = j0; j < j0 + 256; j += 4) {
            const float h0 = hidden[(size_t)(j + 0) * MDIM + m];
            const float h1 = hidden[(size_t)(j + 1) * MDIM + m];
            const float h2 = hidden[(size_t)(j + 2) * MDIM + m];
            const float h3 = hidden[(size_t)(j + 3) * MDIM + m];
            #pragma unroll
            for (int r = 0; r < RPB; r++) {
                const float4 wv = *reinterpret_cast<const float4*>(&s_sc[r * P + j]);
                acc[r] = fmaf(wv.x, h0, acc[r]);
                acc[r] = fmaf(wv.y, h1, acc[r]);
                acc[r] = fmaf(wv.z, h2, acc[r]);
                acc[r] = fmaf(wv.w, h3, acc[r]);
            }
        }

        #pragma unroll
        for (int r = 0; r < RPB; r++)
            s_part[(slice * RPB + r) * 128 + m] = acc[r];
    }
    __syncthreads();

    for (int o = tid; o < RPB * 128; o += NTHREADS) {
        const int r  = o >> 7;
        const int mm = o & 127;
        const float v = s_part[(0 * RPB + r) * 128 + mm]
                      + s_part[(1 * RPB + r) * 128 + mm]
                      + s_part[(2 * RPB + r) * 128 + mm]
                      + s_part[(3 * RPB + r) * 128 + mm];
        out[(size_t)(i0 + r) * MDIM + mm] = v;
    }
}

extern "C" void kernel_launch(void* const* d_in, const int* in_sizes, int n_in,
                              void* d_out, int out_size)
{
    (void)in_sizes; (void)n_in; (void)out_size;
    const float* hidden = (const float*)d_in[0];   // [1024,128]
    const float* rela   = (const float*)d_in[1];   // [1024,1024,128]
    // d_in[2] = corr_index : unused
    const int*   nei    = (const int*)  d_in[3];   // [1024,1024]
    const float* att_w  = (const float*)d_in[4];   // [128]
    const float* att_b  = (const float*)d_in[5];   // [1]
    float* out = (float*)d_out;                    // [1024,128] f32

    si_scores_kernel<<<P * P / (128 * 8), 256>>>(rela, att_w, att_b);

    cudaFuncSetAttribute(si_softmax_gemm_kernel,
                         cudaFuncAttributeMaxDynamicSharedMemorySize,
                         SMEM_BYTES);
    si_softmax_gemm_kernel<<<P / RPB, NTHREADS, SMEM_BYTES>>>(hidden, nei, out);
}

// round 3
// speedup vs baseline: 1.7642x; 1.1775x over previous
#include <cuda_runtime.h>
#include <cstdint>

#define P    1024
#define RDIM 128
#define MDIM 128

// 4 MB scratch: final softmax weights (device global — allocation-free).
__device__ float g_wbuf[P * P];

// =====================================================================
// Kernel A: one block per output row i.
//   scores[j] = rela[i,j,:] . att_w  (8 warps x 128 j each, pipelined)
//   then in-block masked softmax -> g_wbuf[i, :]
// =====================================================================
__global__ __launch_bounds__(256)
void si_row_kernel(const float* __restrict__ rela,
                   const int*   __restrict__ nei,
                   const float* __restrict__ att_w,
                   const float* __restrict__ att_b,
                   float*       __restrict__ wout)
{
    __shared__ float s_sc[P];      // raw scores for this row
    __shared__ float s_red[16];    // cross-warp reduce scratch

    const int tid  = threadIdx.x;
    const int lane = tid & 31;
    const int warp = tid >> 5;     // 0..7
    const int i    = blockIdx.x;

    const float4 w4 = reinterpret_cast<const float4*>(att_w)[lane];

    // each warp owns j in [warp*128, warp*128+128), 16 iters x 8 rows
    const float* base = rela + ((size_t)i * P + (size_t)warp * 128) * RDIM;

    // ---- pipelined dot products ----
    float4 cur[8], nxt[8];
    #pragma unroll
    for (int k = 0; k < 8; k++)
        cur[k] = reinterpret_cast<const float4*>(base + (size_t)k * RDIM)[lane];

    #pragma unroll 1
    for (int it = 0; it < 16; it++) {
        // prefetch next 8 rows while we reduce the current 8
        if (it < 15) {
            const float* nb = base + (size_t)(it + 1) * 8 * RDIM;
            #pragma unroll
            for (int k = 0; k < 8; k++)
                nxt[k] = reinterpret_cast<const float4*>(nb + (size_t)k * RDIM)[lane];
        }

        float d[8];
        #pragma unroll
        for (int k = 0; k < 8; k++)
            d[k] = fmaf(cur[k].x, w4.x,
                   fmaf(cur[k].y, w4.y,
                   fmaf(cur[k].z, w4.z, cur[k].w * w4.w)));

        // butterfly stages 16, 8, 4 on all 8 values (24 shfls)
        #pragma unroll
        for (int s = 16; s >= 4; s >>= 1) {
            #pragma unroll
            for (int k = 0; k < 8; k++)
                d[k] += __shfl_xor_sync(0xFFFFFFFFu, d[k], s);
        }
        // now d[k] holds 4 partials indexed by (lane&3).
        // pack: lane group g = lane>>2 takes row g's partial.
        const int g = lane >> 2;
        float v = d[0];
        v = (g == 1) ? d[1] : v;
        v = (g == 2) ? d[2] : v;
        v = (g == 3) ? d[3] : v;
        v = (g == 4) ? d[4] : v;
        v = (g == 5) ? d[5] : v;
        v = (g == 6) ? d[6] : v;
        v = (g == 7) ? d[7] : v;
        // finish within each 4-lane group (2 shfls)
        v += __shfl_xor_sync(0xFFFFFFFFu, v, 1);
        v += __shfl_xor_sync(0xFFFFFFFFu, v, 2);
        if ((lane & 3) == 0)
            s_sc[warp * 128 + it * 8 + g] = v;

        #pragma unroll
        for (int k = 0; k < 8; k++) cur[k] = nxt[k];
    }
    __syncthreads();

    // ---- masked softmax over the 1024 scores ----
    const float b = att_b[0];
    const int* nrow = nei + (size_t)i * P;

    float vals[4];
    unsigned mbits = 0;
    float vmax = -1e30f;
    #pragma unroll
    for (int k = 0; k < 4; k++) {
        const int j = tid + k * 256;
        const bool m = (nrow[j] > 0);
        if (m) mbits |= (1u << k);
        const float v = m ? (s_sc[j] + b) : -1e-6f;
        vals[k] = v;
        vmax = fmaxf(vmax, v);
    }
    #pragma unroll
    for (int s = 16; s; s >>= 1)
        vmax = fmaxf(vmax, __shfl_xor_sync(0xFFFFFFFFu, vmax, s));
    if (lane == 0) s_red[warp] = vmax;
    __syncthreads();
    {
        float t = s_red[lane & 7];
        #pragma unroll
        for (int s = 4; s; s >>= 1)
            t = fmaxf(t, __shfl_xor_sync(0xFFFFFFFFu, t, s));
        vmax = t;  // every lane of every warp computes the same block max
    }

    float vsum = 0.0f;
    #pragma unroll
    for (int k = 0; k < 4; k++) {
        const float e = __expf(vals[k] - vmax);
        vals[k] = e;
        vsum += e;
    }
    #pragma unroll
    for (int s = 16; s; s >>= 1)
        vsum += __shfl_xor_sync(0xFFFFFFFFu, vsum, s);
    __syncthreads();   // protect s_red reuse
    if (lane == 0) s_red[8 + warp] = vsum;
    __syncthreads();
    {
        float t = s_red[8 + (lane & 7)];
        #pragma unroll
        for (int s = 4; s; s >>= 1)
            t += __shfl_xor_sync(0xFFFFFFFFu, t, s);
        vsum = t;
    }
    const float inv = 1.0f / vsum;

    float* wrow = wout + (size_t)i * P;
    #pragma unroll
    for (int k = 0; k < 4; k++) {
        const int j = tid + k * 256;
        wrow[j] = ((mbits >> k) & 1u) ? vals[k] * inv : 0.0f;
    }
}

// =====================================================================
// Kernel B: pure GEMM  out[i, m] = sum_j W[i, j] * hidden[j, m]
// Grid 128 x 512 threads, 8 output rows per block; weights staged in smem.
// =====================================================================
#define RPB  8
#define NTHREADS 512
#define SMEM_FLOATS (RPB*1024 + 4*RPB*128)
#define SMEM_BYTES  (SMEM_FLOATS * 4)

__global__ __launch_bounds__(NTHREADS, 1)
void si_gemm_kernel(const float* __restrict__ hidden,
                    const float* __restrict__ wsrc_g,
                    float*       __restrict__ out)
{
    extern __shared__ float smem[];
    float* s_w   = smem;                  // RPB * 1024
    float* s_part= s_w + RPB * 1024;      // 4 * RPB * 128

    const int tid = threadIdx.x;
    const int i0  = blockIdx.x * RPB;

    // stage weights: 8 rows x 1024 = 32 KB, coalesced float4
    {
        const float4* src = reinterpret_cast<const float4*>(wsrc_g + (size_t)i0 * P);
        float4* dst = reinterpret_cast<float4*>(s_w);
        #pragma unroll
        for (int t = 0; t < (RPB * P / 4) / NTHREADS; t++)
            dst[tid + t * NTHREADS] = src[tid + t * NTHREADS];
    }
    __syncthreads();

    {
        const int m     = tid & 127;
        const int slice = tid >> 7;   // 0..3
        const int j0    = slice * 256;

        float acc[RPB];
        #pragma unroll
        for (int r = 0; r < RPB; r++) acc[r] = 0.0f;

        #pragma unroll 1
        for (int j = j0; j < j0 + 256; j += 4) {
            const float h0 = hidden[(size_t)(j + 0) * MDIM + m];
            const float h1 = hidden[(size_t)(j + 1) * MDIM + m];
            const float h2 = hidden[(size_t)(j + 2) * MDIM + m];
            const float h3 = hidden[(size_t)(j + 3) * MDIM + m];
            #pragma unroll
            for (int r = 0; r < RPB; r++) {
                const float4 wv = *reinterpret_cast<const float4*>(&s_w[r * P + j]);
                acc[r] = fmaf(wv.x, h0, acc[r]);
                acc[r] = fmaf(wv.y, h1, acc[r]);
                acc[r] = fmaf(wv.z, h2, acc[r]);
                acc[r] = fmaf(wv.w, h3, acc[r]);
            }
        }

        #pragma unroll
        for (int r = 0; r < RPB; r++)
            s_part[(slice * RPB + r) * 128 + m] = acc[r];
    }
    __syncthreads();

    for (int o = tid; o < RPB * 128; o += NTHREADS) {
        const int r  = o >> 7;
        const int mm = o & 127;
        const float v = s_part[(0 * RPB + r) * 128 + mm]
                      + s_part[(1 * RPB + r) * 128 + mm]
                      + s_part[(2 * RPB + r) * 128 + mm]
                      + s_part[(3 * RPB + r) * 128 + mm];
        out[(size_t)(i0 + r) * MDIM + mm] = v;
    }
}

extern "C" void kernel_launch(void* const* d_in, const int* in_sizes, int n_in,
                              void* d_out, int out_size)
{
    (void)in_sizes; (void)n_in; (void)out_size;
    const float* hidden = (const float*)d_in[0];   // [1024,128]
    const float* rela   = (const float*)d_in[1];   // [1024,1024,128]
    // d_in[2] = corr_index : unused
    const int*   nei    = (const int*)  d_in[3];   // [1024,1024]
    const float* att_w  = (const float*)d_in[4];   // [128]
    const float* att_b  = (const float*)d_in[5];   // [1]
    float* out = (float*)d_out;                    // [1024,128] f32

    float* wbuf;
    cudaGetSymbolAddress((void**)&wbuf, g_wbuf);

    si_row_kernel<<<P, 256>>>(rela, nei, att_w, att_b, wbuf);

    cudaFuncSetAttribute(si_gemm_kernel,
                         cudaFuncAttributeMaxDynamicSharedMemorySize,
                         SMEM_BYTES);
    si_gemm_kernel<<<P / RPB, NTHREADS, SMEM_BYTES>>>(hidden, wbuf, out);
}

// round 4
// speedup vs baseline: 1.8975x; 1.0756x over previous
#include <cuda_runtime.h>
#include <cstdint>

#define P    1024
#define RDIM 128
#define MDIM 128

// Scratch (device globals — allocation-free).
__device__ __align__(16) float g_wbuf[P * P];            // softmax weights, 4 MB
__device__ __align__(16) float g_part[4 * P * MDIM];     // split-K partials, 2 MB

// =====================================================================
// Kernel A: one block per output row i.
//   scores[j] = rela[i,j,:] . att_w  (8 warps x 128 j each, pipelined)
//   then in-block masked softmax -> g_wbuf[i, :]
// =====================================================================
__global__ __launch_bounds__(256)
void si_row_kernel(const float* __restrict__ rela,
                   const int*   __restrict__ nei,
                   const float* __restrict__ att_w,
                   const float* __restrict__ att_b,
                   float*       __restrict__ wout)
{
    __shared__ float s_sc[P];      // raw scores for this row
    __shared__ float s_red[16];    // cross-warp reduce scratch

    const int tid  = threadIdx.x;
    const int lane = tid & 31;
    const int warp = tid >> 5;     // 0..7
    const int i    = blockIdx.x;

    const float4 w4 = reinterpret_cast<const float4*>(att_w)[lane];

    const float* base = rela + ((size_t)i * P + (size_t)warp * 128) * RDIM;

    float4 cur[8], nxt[8];
    #pragma unroll
    for (int k = 0; k < 8; k++)
        cur[k] = reinterpret_cast<const float4*>(base + (size_t)k * RDIM)[lane];

    #pragma unroll 1
    for (int it = 0; it < 16; it++) {
        if (it < 15) {
            const float* nb = base + (size_t)(it + 1) * 8 * RDIM;
            #pragma unroll
            for (int k = 0; k < 8; k++)
                nxt[k] = reinterpret_cast<const float4*>(nb + (size_t)k * RDIM)[lane];
        }

        float d[8];
        #pragma unroll
        for (int k = 0; k < 8; k++)
            d[k] = fmaf(cur[k].x, w4.x,
                   fmaf(cur[k].y, w4.y,
                   fmaf(cur[k].z, w4.z, cur[k].w * w4.w)));

        #pragma unroll
        for (int s = 16; s >= 4; s >>= 1) {
            #pragma unroll
            for (int k = 0; k < 8; k++)
                d[k] += __shfl_xor_sync(0xFFFFFFFFu, d[k], s);
        }
        const int g = lane >> 2;
        float v = d[0];
        v = (g == 1) ? d[1] : v;
        v = (g == 2) ? d[2] : v;
        v = (g == 3) ? d[3] : v;
        v = (g == 4) ? d[4] : v;
        v = (g == 5) ? d[5] : v;
        v = (g == 6) ? d[6] : v;
        v = (g == 7) ? d[7] : v;
        v += __shfl_xor_sync(0xFFFFFFFFu, v, 1);
        v += __shfl_xor_sync(0xFFFFFFFFu, v, 2);
        if ((lane & 3) == 0)
            s_sc[warp * 128 + it * 8 + g] = v;

        #pragma unroll
        for (int k = 0; k < 8; k++) cur[k] = nxt[k];
    }
    __syncthreads();

    // ---- masked softmax over the 1024 scores ----
    const float b = att_b[0];
    const int* nrow = nei + (size_t)i * P;

    float vals[4];
    unsigned mbits = 0;
    float vmax = -1e30f;
    #pragma unroll
    for (int k = 0; k < 4; k++) {
        const int j = tid + k * 256;
        const bool m = (nrow[j] > 0);
        if (m) mbits |= (1u << k);
        const float v = m ? (s_sc[j] + b) : -1e-6f;
        vals[k] = v;
        vmax = fmaxf(vmax, v);
    }
    #pragma unroll
    for (int s = 16; s; s >>= 1)
        vmax = fmaxf(vmax, __shfl_xor_sync(0xFFFFFFFFu, vmax, s));
    if (lane == 0) s_red[warp] = vmax;
    __syncthreads();
    {
        float t = s_red[lane & 7];
        #pragma unroll
        for (int s = 4; s; s >>= 1)
            t = fmaxf(t, __shfl_xor_sync(0xFFFFFFFFu, t, s));
        vmax = t;
    }

    float vsum = 0.0f;
    #pragma unroll
    for (int k = 0; k < 4; k++) {
        const float e = __expf(vals[k] - vmax);
        vals[k] = e;
        vsum += e;
    }
    #pragma unroll
    for (int s = 16; s; s >>= 1)
        vsum += __shfl_xor_sync(0xFFFFFFFFu, vsum, s);
    __syncthreads();
    if (lane == 0) s_red[8 + warp] = vsum;
    __syncthreads();
    {
        float t = s_red[8 + (lane & 7)];
        #pragma unroll
        for (int s = 4; s; s >>= 1)
            t += __shfl_xor_sync(0xFFFFFFFFu, t, s);
        vsum = t;
    }
    const float inv = 1.0f / vsum;

    float* wrow = wout + (size_t)i * P;
    #pragma unroll
    for (int k = 0; k < 4; k++) {
        const int j = tid + k * 256;
        wrow[j] = ((mbits >> k) & 1u) ? vals[k] * inv : 0.0f;
    }
}

// =====================================================================
// Kernel B1: split-K GEMM partials.
// Grid 512 = 128 i-tiles x 4 j-splits; 256 threads.
// Block (it, js): rows [it*8, it*8+8), j in [js*256, js*256+256), all m.
// part[js][i][m] = sum over that j-slice of W[i,j] * hidden[j,m]
// =====================================================================
#define RPB 8

__global__ __launch_bounds__(256)
void si_gemm_part_kernel(const float* __restrict__ hidden,
                         const float* __restrict__ wsrc,
                         float*       __restrict__ part)
{
    __shared__ float s_w[RPB * 256];        // weight slice, 8 KB
    __shared__ float s_part[2 * RPB * 128]; // per-sub partials, 8 KB

    const int tid = threadIdx.x;
    const int it  = blockIdx.x >> 2;        // i-tile 0..127
    const int js  = blockIdx.x & 3;         // j-split 0..3
    const int i0  = it * RPB;
    const int jb  = js * 256;

    // stage weight slice: 8 rows x 256 j, coalesced float4 (2 per thread)
    {
        #pragma unroll
        for (int t = 0; t < 2; t++) {
            const int o = (tid + t * 256) * 4;      // float offset in slice
            const int r = o >> 8;                   // /256
            const int jj = o & 255;
            *reinterpret_cast<float4*>(&s_w[o]) =
                *reinterpret_cast<const float4*>(&wsrc[(size_t)(i0 + r) * P + jb + jj]);
        }
    }
    __syncthreads();

    {
        const int m   = tid & 127;
        const int sub = tid >> 7;    // 0/1, 128 j each
        const int j0  = sub * 128;

        float acc[RPB];
        #pragma unroll
        for (int r = 0; r < RPB; r++) acc[r] = 0.0f;

        #pragma unroll 1
        for (int j = j0; j < j0 + 128; j += 4) {
            const float h0 = hidden[(size_t)(jb + j + 0) * MDIM + m];
            const float h1 = hidden[(size_t)(jb + j + 1) * MDIM + m];
            const float h2 = hidden[(size_t)(jb + j + 2) * MDIM + m];
            const float h3 = hidden[(size_t)(jb + j + 3) * MDIM + m];
            #pragma unroll
            for (int r = 0; r < RPB; r++) {
                const float4 wv = *reinterpret_cast<const float4*>(&s_w[r * 256 + j]);
                acc[r] = fmaf(wv.x, h0, acc[r]);
                acc[r] = fmaf(wv.y, h1, acc[r]);
                acc[r] = fmaf(wv.z, h2, acc[r]);
                acc[r] = fmaf(wv.w, h3, acc[r]);
            }
        }

        #pragma unroll
        for (int r = 0; r < RPB; r++)
            s_part[(sub * RPB + r) * 128 + m] = acc[r];
    }
    __syncthreads();

    // combine the 2 subs, write partial: part[js*P*M + (i0+r)*M + m]
    #pragma unroll
    for (int t = 0; t < 4; t++) {
        const int o = tid + t * 256;        // 0..1023
        const int r = o >> 7;
        const int mm = o & 127;
        part[(size_t)js * P * MDIM + (size_t)(i0 + r) * MDIM + mm] =
            s_part[o] + s_part[RPB * 128 + o];
    }
}

// =====================================================================
// Kernel B2: reduce 4 split-K partials -> out. 131072 floats = 32768 f4.
// =====================================================================
__global__ __launch_bounds__(256)
void si_gemm_reduce_kernel(const float* __restrict__ part,
                           float*       __restrict__ out)
{
    const int e4 = blockIdx.x * 256 + threadIdx.x;   // 0..32767
    const float4* p4 = reinterpret_cast<const float4*>(part);
    const float4 a = p4[0 * 32768 + e4];
    const float4 b = p4[1 * 32768 + e4];
    const float4 c = p4[2 * 32768 + e4];
    const float4 d = p4[3 * 32768 + e4];
    float4 s;
    s.x = (a.x + b.x) + (c.x + d.x);
    s.y = (a.y + b.y) + (c.y + d.y);
    s.z = (a.z + b.z) + (c.z + d.z);
    s.w = (a.w + b.w) + (c.w + d.w);
    reinterpret_cast<float4*>(out)[e4] = s;
}

extern "C" void kernel_launch(void* const* d_in, const int* in_sizes, int n_in,
                              void* d_out, int out_size)
{
    (void)in_sizes; (void)n_in; (void)out_size;
    const float* hidden = (const float*)d_in[0];   // [1024,128]
    const float* rela   = (const float*)d_in[1];   // [1024,1024,128]
    // d_in[2] = corr_index : unused
    const int*   nei    = (const int*)  d_in[3];   // [1024,1024]
    const float* att_w  = (const float*)d_in[4];   // [128]
    const float* att_b  = (const float*)d_in[5];   // [1]
    float* out = (float*)d_out;                    // [1024,128] f32

    float* wbuf;  cudaGetSymbolAddress((void**)&wbuf, g_wbuf);
    float* pbuf;  cudaGetSymbolAddress((void**)&pbuf, g_part);

    si_row_kernel<<<P, 256>>>(rela, nei, att_w, att_b, wbuf);
    si_gemm_part_kernel<<<(P / RPB) * 4, 256>>>(hidden, wbuf, pbuf);
    si_gemm_reduce_kernel<<<P * MDIM / 4 / 256, 256>>>(pbuf, out);
}

// round 5
// speedup vs baseline: 1.9754x; 1.0411x over previous
#include <cuda_runtime.h>
#include <cstdint>

#define P    1024
#define RDIM 128
#define MDIM 128

#define JS   8                       // j-splits in GEMM
#define RPB  16                      // rows per GEMM block

// Scratch (device globals — allocation-free).
__device__ __align__(16) float g_wbuf[P * P];            // softmax weights, 4 MB
__device__ __align__(16) float g_part[JS * P * MDIM];    // split-K partials, 4 MB

// =====================================================================
// Kernel A: one block per output row i.
//   scores[j] = rela[i,j,:] . att_w  (8 warps x 128 j each, pipelined)
//   then in-block masked softmax -> g_wbuf[i, :]
// =====================================================================
__global__ __launch_bounds__(256)
void si_row_kernel(const float* __restrict__ rela,
                   const int*   __restrict__ nei,
                   const float* __restrict__ att_w,
                   const float* __restrict__ att_b,
                   float*       __restrict__ wout)
{
    __shared__ float s_sc[P];      // raw scores for this row
    __shared__ int   s_nei[P];     // prefetched neighbor mask row
    __shared__ float s_red[16];    // cross-warp reduce scratch

    const int tid  = threadIdx.x;
    const int lane = tid & 31;
    const int warp = tid >> 5;     // 0..7
    const int i    = blockIdx.x;

    // prefetch nei row early (overlaps with the big stream)
    {
        const int4 nv = reinterpret_cast<const int4*>(nei + (size_t)i * P)[tid];
        reinterpret_cast<int4*>(s_nei)[tid] = nv;
    }

    const float4 w4 = reinterpret_cast<const float4*>(att_w)[lane];

    const float* base = rela + ((size_t)i * P + (size_t)warp * 128) * RDIM;

    float4 cur[8], nxt[8];
    #pragma unroll
    for (int k = 0; k < 8; k++)
        cur[k] = reinterpret_cast<const float4*>(base + (size_t)k * RDIM)[lane];

    #pragma unroll 1
    for (int it = 0; it < 16; it++) {
        if (it < 15) {
            const float* nb = base + (size_t)(it + 1) * 8 * RDIM;
            #pragma unroll
            for (int k = 0; k < 8; k++)
                nxt[k] = reinterpret_cast<const float4*>(nb + (size_t)k * RDIM)[lane];
        }

        float d[8];
        #pragma unroll
        for (int k = 0; k < 8; k++)
            d[k] = fmaf(cur[k].x, w4.x,
                   fmaf(cur[k].y, w4.y,
                   fmaf(cur[k].z, w4.z, cur[k].w * w4.w)));

        #pragma unroll
        for (int s = 16; s >= 4; s >>= 1) {
            #pragma unroll
            for (int k = 0; k < 8; k++)
                d[k] += __shfl_xor_sync(0xFFFFFFFFu, d[k], s);
        }
        const int g = lane >> 2;
        float v = d[0];
        v = (g == 1) ? d[1] : v;
        v = (g == 2) ? d[2] : v;
        v = (g == 3) ? d[3] : v;
        v = (g == 4) ? d[4] : v;
        v = (g == 5) ? d[5] : v;
        v = (g == 6) ? d[6] : v;
        v = (g == 7) ? d[7] : v;
        v += __shfl_xor_sync(0xFFFFFFFFu, v, 1);
        v += __shfl_xor_sync(0xFFFFFFFFu, v, 2);
        if ((lane & 3) == 0)
            s_sc[warp * 128 + it * 8 + g] = v;

        #pragma unroll
        for (int k = 0; k < 8; k++) cur[k] = nxt[k];
    }
    __syncthreads();

    // ---- masked softmax over the 1024 scores ----
    const float b = att_b[0];

    float vals[4];
    unsigned mbits = 0;
    float vmax = -1e30f;
    #pragma unroll
    for (int k = 0; k < 4; k++) {
        const int j = tid + k * 256;
        const bool m = (s_nei[j] > 0);
        if (m) mbits |= (1u << k);
        const float v = m ? (s_sc[j] + b) : -1e-6f;
        vals[k] = v;
        vmax = fmaxf(vmax, v);
    }
    #pragma unroll
    for (int s = 16; s; s >>= 1)
        vmax = fmaxf(vmax, __shfl_xor_sync(0xFFFFFFFFu, vmax, s));
    if (lane == 0) s_red[warp] = vmax;
    __syncthreads();
    {
        float t = s_red[lane & 7];
        #pragma unroll
        for (int s = 4; s; s >>= 1)
            t = fmaxf(t, __shfl_xor_sync(0xFFFFFFFFu, t, s));
        vmax = t;
    }

    float vsum = 0.0f;
    #pragma unroll
    for (int k = 0; k < 4; k++) {
        const float e = __expf(vals[k] - vmax);
        vals[k] = e;
        vsum += e;
    }
    #pragma unroll
    for (int s = 16; s; s >>= 1)
        vsum += __shfl_xor_sync(0xFFFFFFFFu, vsum, s);
    __syncthreads();
    if (lane == 0) s_red[8 + warp] = vsum;
    __syncthreads();
    {
        float t = s_red[8 + (lane & 7)];
        #pragma unroll
        for (int s = 4; s; s >>= 1)
            t += __shfl_xor_sync(0xFFFFFFFFu, t, s);
        vsum = t;
    }
    const float inv = 1.0f / vsum;

    float* wrow = wout + (size_t)i * P;
    #pragma unroll
    for (int k = 0; k < 4; k++) {
        const int j = tid + k * 256;
        wrow[j] = ((mbits >> k) & 1u) ? vals[k] * inv : 0.0f;
    }
}

// =====================================================================
// Kernel B1: split-K GEMM partials.
// Grid 512 = 64 i-tiles x 8 j-splits; 256 threads.
// Block (it, js): rows [it*16, it*16+16), j in [js*128, js*128+128), all m.
// part[js][i][m] = sum over that j-slice of W[i,j] * hidden[j,m]
// =====================================================================
__global__ __launch_bounds__(256)
void si_gemm_part_kernel(const float* __restrict__ hidden,
                         const float* __restrict__ wsrc,
                         float*       __restrict__ part)
{
    __shared__ float s_w[RPB * 128];        // weight slice, 8 KB
    __shared__ float s_part[2 * RPB * 128]; // per-sub partials, 16 KB

    const int tid = threadIdx.x;
    const int it  = blockIdx.x >> 3;        // i-tile 0..63
    const int js  = blockIdx.x & 7;         // j-split 0..7
    const int i0  = it * RPB;
    const int jb  = js * 128;

    // stage weight slice: 16 rows x 128 j = 2048 floats, 2 float4/thread
    #pragma unroll
    for (int t = 0; t < 2; t++) {
        const int o = (tid + t * 256) * 4;  // float offset in slice
        const int r = o >> 7;
        const int jj = o & 127;
        *reinterpret_cast<float4*>(&s_w[o]) =
            *reinterpret_cast<const float4*>(&wsrc[(size_t)(i0 + r) * P + jb + jj]);
    }
    __syncthreads();

    {
        const int m   = tid & 127;
        const int sub = tid >> 7;    // 0/1, 64 j each
        const int j0  = sub * 64;

        float acc[RPB];
        #pragma unroll
        for (int r = 0; r < RPB; r++) acc[r] = 0.0f;

        #pragma unroll 1
        for (int j = j0; j < j0 + 64; j += 4) {
            const float h0 = hidden[(size_t)(jb + j + 0) * MDIM + m];
            const float h1 = hidden[(size_t)(jb + j + 1) * MDIM + m];
            const float h2 = hidden[(size_t)(jb + j + 2) * MDIM + m];
            const float h3 = hidden[(size_t)(jb + j + 3) * MDIM + m];
            #pragma unroll
            for (int r = 0; r < RPB; r++) {
                const float4 wv = *reinterpret_cast<const float4*>(&s_w[r * 128 + j]);
                acc[r] = fmaf(wv.x, h0, acc[r]);
                acc[r] = fmaf(wv.y, h1, acc[r]);
                acc[r] = fmaf(wv.z, h2, acc[r]);
                acc[r] = fmaf(wv.w, h3, acc[r]);
            }
        }

        #pragma unroll
        for (int r = 0; r < RPB; r++)
            s_part[(sub * RPB + r) * 128 + m] = acc[r];
    }
    __syncthreads();

    // combine the 2 subs, write partial: part[js][i0+r][m]
    #pragma unroll
    for (int t = 0; t < 8; t++) {
        const int o = tid + t * 256;        // 0..2047
        const int r = o >> 7;
        const int mm = o & 127;
        part[(size_t)js * P * MDIM + (size_t)(i0 + r) * MDIM + mm] =
            s_part[o] + s_part[RPB * 128 + o];
    }
}

// =====================================================================
// Kernel B2: reduce 8 split-K partials -> out. 131072 floats = 32768 f4.
// =====================================================================
__global__ __launch_bounds__(256)
void si_gemm_reduce_kernel(const float* __restrict__ part,
                           float*       __restrict__ out)
{
    const int e4 = blockIdx.x * 256 + threadIdx.x;   // 0..32767
    const float4* p4 = reinterpret_cast<const float4*>(part);
    float4 s = p4[e4];
    #pragma unroll
    for (int k = 1; k < JS; k++) {
        const float4 a = p4[(size_t)k * 32768 + e4];
        s.x += a.x; s.y += a.y; s.z += a.z; s.w += a.w;
    }
    reinterpret_cast<float4*>(out)[e4] = s;
}

extern "C" void kernel_launch(void* const* d_in, const int* in_sizes, int n_in,
                              void* d_out, int out_size)
{
    (void)in_sizes; (void)n_in; (void)out_size;
    const float* hidden = (const float*)d_in[0];   // [1024,128]
    const float* rela   = (const float*)d_in[1];   // [1024,1024,128]
    // d_in[2] = corr_index : unused
    const int*   nei    = (const int*)  d_in[3];   // [1024,1024]
    const float* att_w  = (const float*)d_in[4];   // [128]
    const float* att_b  = (const float*)d_in[5];   // [1]
    float* out = (float*)d_out;                    // [1024,128] f32

    float* wbuf;  cudaGetSymbolAddress((void**)&wbuf, g_wbuf);
    float* pbuf;  cudaGetSymbolAddress((void**)&pbuf, g_part);

    si_row_kernel<<<P, 256>>>(rela, nei, att_w, att_b, wbuf);
    si_gemm_part_kernel<<<(P / RPB) * JS, 256>>>(hidden, wbuf, pbuf);
    si_gemm_reduce_kernel<<<P * MDIM / 4 / 256, 256>>>(pbuf, out);
}